// round 15
// baseline (speedup 1.0000x reference)
#include <cuda_runtime.h>
#include <cuda_bf16.h>
#include <cstdint>

#define N_NODES 50000
#define N_EDGES 600000
#define NFEAT   7
#define EFEAT   4
#define H       128
#define L_LAYERS 4
#define K_HOPS   3
#define WSTR    512               // wide buffer row stride (h|p1|p2|p3)
#define NCHUNK_TOT 34             // 2 (eW2) + 4*8 (tagW layers)

// prepped weight chunk: 32 kpair-rows x 136 u32 (padded) per hi/lo image
#define B_IMG_U32 4352            // 32*136
#define B_CHUNK_U32 (2 * B_IMG_U32)          // 8704 u32 = 34816 B = 2176 x 16B
#define B_CHUNK_V16 2176

// ---------------- scratch (static device globals; no allocation) -------------
__device__ float    g_hsum[N_NODES * H];
__device__ float    g_wide[(size_t)N_NODES * WSTR];
__device__ int      g_deg[N_NODES];
__device__ float    g_dinv[N_NODES];
__device__ int      g_ptr[N_NODES + 1];
__device__ int      g_cur[N_NODES];
__device__ int      g_srcs[N_EDGES];
__device__ float    g_eaperm[(size_t)N_EDGES * 4];   // edge attrs in CSR order
__device__ float    g_normv[N_EDGES];
__device__ int      g_part[64];
__device__ uint32_t g_wprep[(size_t)NCHUNK_TOT * B_CHUNK_U32];
__device__ float    g_wfold[WSTR * 2];       // folded tagW[3]@outW, [512][2]
__device__ float    g_yb[2];                 // folded bias

#define FLAG_RELU     2
#define FLAG_BIAS     4
#define FLAG_DEGSCALE 8

// ============================================================================
// helpers
// ============================================================================
__device__ __forceinline__ uint32_t smem_u32(const void* p) {
    uint32_t a;
    asm("{ .reg .u64 t; cvta.to.shared.u64 t, %1; cvt.u32.u64 %0, t; }" : "=r"(a) : "l"(p));
    return a;
}
__device__ __forceinline__ void cp_async16(uint32_t saddr, const void* g) {
    asm volatile("cp.async.cg.shared.global [%0], [%1], 16;" :: "r"(saddr), "l"(g) : "memory");
}
#define CP_COMMIT() asm volatile("cp.async.commit_group;" ::: "memory")
#define CP_WAIT0()  asm volatile("cp.async.wait_group 0;" ::: "memory")
#define CP_WAIT3()  asm volatile("cp.async.wait_group 3;" ::: "memory")

// fp32 pair -> (bf16x2 hi word, bf16x2 lo word); element a in low half.
__device__ __forceinline__ void cvt2(float a, float b, uint32_t& hw, uint32_t& lw) {
    __nv_bfloat16 ha = __float2bfloat16_rn(a), hb = __float2bfloat16_rn(b);
    __nv_bfloat162 hp; hp.x = ha; hp.y = hb;
    hw = *(uint32_t*)&hp;
    __nv_bfloat162 lp = __floats2bfloat162_rn(a - __bfloat162float(ha), b - __bfloat162float(hb));
    lw = *(uint32_t*)&lp;
}

__device__ __forceinline__ void mma16816(float* c,
    uint32_t a0, uint32_t a1, uint32_t a2, uint32_t a3, uint32_t b0, uint32_t b1)
{
    asm volatile(
        "mma.sync.aligned.m16n8k16.row.col.f32.bf16.bf16.f32 "
        "{%0,%1,%2,%3},{%4,%5,%6,%7},{%8,%9},{%0,%1,%2,%3};"
        : "+f"(c[0]), "+f"(c[1]), "+f"(c[2]), "+f"(c[3])
        : "r"(a0), "r"(a1), "r"(a2), "r"(a3), "r"(b0), "r"(b1));
}

// ============================================================================
// CSR build
// ============================================================================
__global__ void k_init() {
    int i = blockIdx.x * blockDim.x + threadIdx.x;
    if (i < N_NODES) g_deg[i] = 0;
}
__global__ void k_count(const int* __restrict__ ei) {
    int e = blockIdx.x * blockDim.x + threadIdx.x;
    if (e < N_EDGES) atomicAdd(&g_deg[ei[N_EDGES + e]], 1);
}
// phase 1 of scan; also computes dinv (reads deg anyway)
__global__ void k_scan1() {
    int i = blockIdx.x * 1024 + threadIdx.x;
    int v = (i < N_NODES) ? g_deg[i] : 0;
    if (i < N_NODES) g_dinv[i] = (v > 0) ? rsqrtf((float)v) : 0.0f;
    __shared__ int s[32];
    int l = threadIdx.x & 31, w = threadIdx.x >> 5;
    int t0 = v;
    #pragma unroll
    for (int o = 16; o; o >>= 1) t0 += __shfl_xor_sync(0xFFFFFFFFu, t0, o);
    if (l == 0) s[w] = t0;
    __syncthreads();
    if (threadIdx.x < 32) {
        int t = s[threadIdx.x];
        #pragma unroll
        for (int o = 16; o; o >>= 1) t += __shfl_xor_sync(0xFFFFFFFFu, t, o);
        if (threadIdx.x == 0) g_part[blockIdx.x] = t;
    }
}
// warp-parallel scan of block partials (nblk <= 64)
__global__ void k_scan2(int nblk) {
    int t = threadIdx.x;            // 64 threads
    int l = t & 31, w = t >> 5;
    int v = (t < nblk) ? g_part[t] : 0;
    int x = v;
    #pragma unroll
    for (int o = 1; o < 32; o <<= 1) {
        int u = __shfl_up_sync(0xFFFFFFFFu, x, o);
        if (l >= o) x += u;
    }
    __shared__ int s[2];
    if (l == 31) s[w] = x;
    __syncthreads();
    int incl = x + ((w == 1) ? s[0] : 0);
    if (t < nblk) g_part[t] = incl - v;    // exclusive
    if (t == nblk - 1) g_ptr[N_NODES] = incl;
}
// phase 3: per-node exclusive prefix; also zeroes cursor for k_fill
__global__ void k_scan3() {
    int i = blockIdx.x * 1024 + threadIdx.x;
    int v = (i < N_NODES) ? g_deg[i] : 0;
    int l = threadIdx.x & 31, w = threadIdx.x >> 5;
    int x = v;
    #pragma unroll
    for (int o = 1; o < 32; o <<= 1) { int t = __shfl_up_sync(0xFFFFFFFFu, x, o); if (l >= o) x += t; }
    __shared__ int s[32];
    if (l == 31) s[w] = x;
    __syncthreads();
    if (threadIdx.x < 32) {
        int y = s[threadIdx.x];
        int z = y;
        #pragma unroll
        for (int o = 1; o < 32; o <<= 1) { int t = __shfl_up_sync(0xFFFFFFFFu, z, o); if (threadIdx.x >= o) z += t; }
        s[threadIdx.x] = z - y;
    }
    __syncthreads();
    if (i < N_NODES) {
        g_ptr[i] = g_part[blockIdx.x] + s[w] + x - v;
        g_cur[i] = 0;
    }
}
// fill CSR; also permute edge attrs into CSR order (kills eids indirection)
__global__ void k_fill(const int* __restrict__ ei, const float* __restrict__ ea) {
    int e = blockIdx.x * blockDim.x + threadIdx.x;
    if (e < N_EDGES) {
        int r = ei[e];
        int c = ei[N_EDGES + e];
        int pos = g_ptr[c] + atomicAdd(&g_cur[c], 1);
        g_srcs[pos]  = r;
        g_normv[pos] = g_dinv[r] * g_dinv[c];
        float4 av = *(const float4*)&ea[(size_t)e * 4];
        *(float4*)&g_eaperm[(size_t)pos * 4] = av;
    }
}

// ============================================================================
// Weight prep: per 64-K chunk, build bf16 hi/lo images in b-fragment layout.
// ============================================================================
__global__ __launch_bounds__(128) void k_prepw(const float* __restrict__ eW2,
                                               const float* __restrict__ tagW) {
    int b = blockIdx.x;
    const float* src; int k0;
    if (b < 2) { src = eW2; k0 = b * 64; }
    else { int c = b - 2; src = tagW + (size_t)(c >> 3) * 512 * 128; k0 = (c & 7) * 64; }
    int n = threadIdx.x;
    uint32_t* dh = g_wprep + (size_t)b * B_CHUNK_U32;
    uint32_t* dl = dh + B_IMG_U32;
    #pragma unroll 4
    for (int kp = 0; kp < 32; kp++) {
        float f0 = src[(size_t)(k0 + 2 * kp)     * 128 + n];
        float f1 = src[(size_t)(k0 + 2 * kp + 1) * 128 + n];
        uint32_t hw, lw;
        cvt2(f0, f1, hw, lw);
        dh[kp * 136 + n] = hw;
        dl[kp * 136 + n] = lw;
    }
}

// ============================================================================
// Fold layer-3 weights through the output projection.
// ============================================================================
__global__ __launch_bounds__(512) void k_foldw(
    const float* __restrict__ tagW, const float* __restrict__ tagb,
    const float* __restrict__ outW, const float* __restrict__ outb)
{
    int m = threadIdx.x;   // 0..511
    const float* wrow = tagW + ((size_t)(3 * (K_HOPS + 1)) * H + m) * H;
    float s0 = 0.f, s1 = 0.f;
    #pragma unroll 8
    for (int c = 0; c < H; c++) {
        float t = wrow[c];
        s0 += t * outW[c * 2 + 0];
        s1 += t * outW[c * 2 + 1];
    }
    g_wfold[m * 2 + 0] = s0;
    g_wfold[m * 2 + 1] = s1;
    if (m < 2) {
        float b = outb[m];
        for (int c = 0; c < H; c++) b += tagb[3 * H + c] * outW[c * 2 + m];
        g_yb[m] = b;
    }
}

// ============================================================================
// Per-node precompute for the edge MLP:
//   base[v] = eb1 + x[v] @ W1[0:7]    -> wide cols [256,384)
//   xW[v]   =       x[v] @ W1[7:14]   -> wide cols [128,256)
// ============================================================================
__global__ __launch_bounds__(256) void k_xw(
    const float* __restrict__ x, const float* __restrict__ eW1,
    const float* __restrict__ eb1, float* __restrict__ wide)
{
    __shared__ float sW[14 * H];
    __shared__ float sb[H];
    int tid = threadIdx.x;
    #pragma unroll
    for (int i = 0; i < 7; i++) sW[tid + i * 256] = eW1[tid + i * 256];
    if (tid < H) sb[tid] = eb1[tid];
    __syncthreads();

    int lid = tid & 31;
    int v = (blockIdx.x * blockDim.x + tid) >> 5;
    if (v >= N_NODES) return;

    float xv[7];
    #pragma unroll
    for (int f = 0; f < 7; f++) xv[f] = x[v * NFEAT + f];

    float4 base = *(const float4*)&sb[lid * 4];
    float4 xw = make_float4(0.f, 0.f, 0.f, 0.f);
    #pragma unroll
    for (int f = 0; f < 7; f++) {
        float4 w0 = *(const float4*)&sW[f * H + lid * 4];
        float4 w1 = *(const float4*)&sW[(7 + f) * H + lid * 4];
        base.x += xv[f] * w0.x; base.y += xv[f] * w0.y;
        base.z += xv[f] * w0.z; base.w += xv[f] * w0.w;
        xw.x   += xv[f] * w1.x; xw.y   += xv[f] * w1.y;
        xw.z   += xv[f] * w1.z; xw.w   += xv[f] * w1.w;
    }
    *(float4*)&wide[(size_t)v * WSTR + 256 + lid * 4] = base;
    *(float4*)&wide[(size_t)v * WSTR + 128 + lid * 4] = xw;
}

// ============================================================================
// Edge MLP stage 1 as a gather kernel (proven R12 version).
// ============================================================================
__global__ __launch_bounds__(256) void k_edge_mlp(
    const float* __restrict__ eW1, const float* __restrict__ wide)
{
    int tid = threadIdx.x;
    int lid = tid & 31;
    int v = (blockIdx.x * blockDim.x + tid) >> 5;
    if (v >= N_NODES) return;

    float4 w14 = *(const float4*)&eW1[14 * H + lid * 4];
    float4 w15 = *(const float4*)&eW1[15 * H + lid * 4];
    float4 w16 = *(const float4*)&eW1[16 * H + lid * 4];
    float4 w17 = *(const float4*)&eW1[17 * H + lid * 4];

    float4 base = *(const float4*)&wide[(size_t)v * WSTR + 256 + lid * 4];

    float a0 = 0.f, a1 = 0.f, a2 = 0.f, a3 = 0.f;
    int beg = g_ptr[v], end = g_ptr[v + 1];
    for (int e = beg; e < end; e++) {
        int s = g_srcs[e];
        float4 eav = *(const float4*)&g_eaperm[(size_t)e * 4];
        float4 xwv = *(const float4*)&wide[(size_t)s * WSTR + 128 + lid * 4];
        float d0 = base.x + xwv.x + eav.x * w14.x + eav.y * w15.x + eav.z * w16.x + eav.w * w17.x;
        float d1 = base.y + xwv.y + eav.x * w14.y + eav.y * w15.y + eav.z * w16.y + eav.w * w17.y;
        float d2 = base.z + xwv.z + eav.x * w14.z + eav.y * w15.z + eav.z * w16.z + eav.w * w17.z;
        float d3 = base.w + xwv.w + eav.x * w14.w + eav.y * w15.w + eav.z * w16.w + eav.w * w17.w;
        a0 += fmaxf(d0, 0.f); a1 += fmaxf(d1, 0.f);
        a2 += fmaxf(d2, 0.f); a3 += fmaxf(d3, 0.f);
    }
    float4 o; o.x = a0; o.y = a1; o.z = a2; o.w = a3;
    *(float4*)&g_hsum[(size_t)v * H + lid * 4] = o;
}

// ============================================================================
// Split-bf16 HMMA GEMM, software-pipelined (proven R7/R12 version).
// ============================================================================
#define SM_AH 0
#define SM_AL 18432
#define SM_B0 36864
#define SM_B1 71680
#define SM_TOT 106496

__global__ __launch_bounds__(256) void k_tgemm(
    const float* __restrict__ A, int strideA, int kchunks, int chunkBase,
    float* __restrict__ C, const float* __restrict__ bias, int flags)
{
    extern __shared__ char smem[];
    uint32_t* sAH = (uint32_t*)(smem + SM_AH);
    uint32_t* sAL = (uint32_t*)(smem + SM_AL);

    int tid  = threadIdx.x;
    int lane = tid & 31, wid = tid >> 5;
    int g = lane >> 2, tg = lane & 3;
    int mrow0 = (wid & 1) * 64;
    int ncol0 = (wid >> 1) * 32;

    int row0 = blockIdx.x * 128;

    int sr = tid >> 1;
    int sh = tid & 1;
    bool svalid = (row0 + sr) < N_NODES;
    const float4* arow = (const float4*)(A + (size_t)(row0 + sr) * strideA) + sh * 8;
    uint32_t* ahw = sAH + sr * 36 + sh * 16;
    uint32_t* alw = sAL + sr * 36 + sh * 16;

    uint32_t sbase = smem_u32(smem);

    float acc[4][4][4];
    #pragma unroll
    for (int mt = 0; mt < 4; mt++)
        #pragma unroll
        for (int nt = 0; nt < 4; nt++)
            #pragma unroll
            for (int j = 0; j < 4; j++) acc[mt][nt][j] = 0.f;

    const uint32_t* aHp = sAH + (mrow0 + g) * 36 + tg;
    const uint32_t* aLp = sAL + (mrow0 + g) * 36 + tg;
    const uint32_t* bH[2], *bL[2];
    bH[0] = (const uint32_t*)(smem + SM_B0) + tg * 136 + ncol0 + g;
    bL[0] = bH[0] + B_IMG_U32;
    bH[1] = (const uint32_t*)(smem + SM_B1) + tg * 136 + ncol0 + g;
    bL[1] = bH[1] + B_IMG_U32;

    const char* wsrc = (const char*)(g_wprep + (size_t)chunkBase * B_CHUNK_U32);

    #pragma unroll
    for (int i = 0; i < 9; i++) {
        int idx = tid + i * 256;
        if (idx < B_CHUNK_V16)
            cp_async16(sbase + SM_B0 + idx * 16, wsrc + idx * 16);
    }
    CP_COMMIT();
    float4 aReg[8];
    #pragma unroll
    for (int c = 0; c < 8; c++)
        aReg[c] = svalid ? arow[c] : make_float4(0.f, 0.f, 0.f, 0.f);

    for (int kc = 0; kc < kchunks; kc++) {
        #pragma unroll
        for (int c = 0; c < 8; c++) {
            uint32_t h0, l0, h1, l1;
            cvt2(aReg[c].x, aReg[c].y, h0, l0);
            cvt2(aReg[c].z, aReg[c].w, h1, l1);
            uint2 hv; hv.x = h0; hv.y = h1;
            uint2 lv; lv.x = l0; lv.y = l1;
            *(uint2*)&ahw[c * 2] = hv;
            *(uint2*)&alw[c * 2] = lv;
        }
        CP_WAIT0();
        __syncthreads();

        if (kc + 1 < kchunks) {
            uint32_t sdst = sbase + (((kc + 1) & 1) ? SM_B1 : SM_B0);
            const char* wn = wsrc + (size_t)(kc + 1) * (B_CHUNK_U32 * 4);
            #pragma unroll
            for (int i = 0; i < 9; i++) {
                int idx = tid + i * 256;
                if (idx < B_CHUNK_V16)
                    cp_async16(sdst + idx * 16, wn + idx * 16);
            }
            CP_COMMIT();
            const float4* ap = arow + (kc + 1) * 16;
            #pragma unroll
            for (int c = 0; c < 8; c++)
                aReg[c] = svalid ? ap[c] : make_float4(0.f, 0.f, 0.f, 0.f);
        }

        const uint32_t* bHp = bH[kc & 1];
        const uint32_t* bLp = bL[kc & 1];
        #pragma unroll
        for (int ks = 0; ks < 4; ks++) {
            uint32_t ah[4][4], al[4][4];
            #pragma unroll
            for (int mt = 0; mt < 4; mt++) {
                int b0 = mt * 16 * 36 + ks * 8;
                ah[mt][0] = aHp[b0];            ah[mt][1] = aHp[b0 + 8 * 36];
                ah[mt][2] = aHp[b0 + 4];        ah[mt][3] = aHp[b0 + 8 * 36 + 4];
                al[mt][0] = aLp[b0];            al[mt][1] = aLp[b0 + 8 * 36];
                al[mt][2] = aLp[b0 + 4];        al[mt][3] = aLp[b0 + 8 * 36 + 4];
            }
            #pragma unroll
            for (int nt = 0; nt < 4; nt++) {
                int bb = ks * 8 * 136 + nt * 8;
                uint32_t bh0 = bHp[bb], bh1 = bHp[bb + 4 * 136];
                uint32_t bl0 = bLp[bb], bl1 = bLp[bb + 4 * 136];
                #pragma unroll
                for (int mt = 0; mt < 4; mt++) {
                    mma16816(acc[mt][nt], ah[mt][0], ah[mt][1], ah[mt][2], ah[mt][3], bh0, bh1);
                    mma16816(acc[mt][nt], ah[mt][0], ah[mt][1], ah[mt][2], ah[mt][3], bl0, bl1);
                    mma16816(acc[mt][nt], al[mt][0], al[mt][1], al[mt][2], al[mt][3], bh0, bh1);
                }
            }
        }
        __syncthreads();
    }

    #pragma unroll
    for (int mt = 0; mt < 4; mt++) {
        #pragma unroll
        for (int half = 0; half < 2; half++) {
            int r = row0 + mrow0 + mt * 16 + g + half * 8;
            if (r >= N_NODES) continue;
            float degs = 1.0f;
            if (flags & FLAG_DEGSCALE) degs = (float)g_deg[r];
            float* crow = C + (size_t)r * WSTR;
            #pragma unroll
            for (int nt = 0; nt < 4; nt++) {
                int col = ncol0 + nt * 8 + tg * 2;
                float v0 = acc[mt][nt][half * 2 + 0];
                float v1 = acc[mt][nt][half * 2 + 1];
                if (flags & FLAG_BIAS) {
                    v0 += bias[col]     * degs;
                    v1 += bias[col + 1] * degs;
                }
                if (flags & FLAG_RELU) { v0 = fmaxf(v0, 0.f); v1 = fmaxf(v1, 0.f); }
                float2 o; o.x = v0; o.y = v1;
                *(float2*)&crow[col] = o;
            }
        }
    }
}

// ============================================================================
// SpMM hop, cp.async depth-4 pipelined: gathers go to the async queue (no
// scoreboard stall); warp always holds 4x512B in flight, FMAs from smem.
// Accumulation order per edge unchanged vs the serial version.
// ============================================================================
#define SPMM_DEPTH 4

__global__ __launch_bounds__(256) void k_spmm(
    const float* __restrict__ P, float* __restrict__ PN)
{
    __shared__ float4 sbuf[8][SPMM_DEPTH][32];   // 16 KB

    int tid = threadIdx.x;
    int lid = tid & 31;
    int wl  = tid >> 5;
    int v = (blockIdx.x * blockDim.x + tid) >> 5;
    if (v >= N_NODES) return;

    int beg = g_ptr[v], end = g_ptr[v + 1];

    uint32_t slot_base = smem_u32(&sbuf[wl][0][lid]);
    // slot d address: slot_base + d * 512

    // prologue: issue first DEPTH gathers (one commit group per edge)
    #pragma unroll
    for (int d = 0; d < SPMM_DEPTH; d++) {
        if (beg + d < end) {
            int s = g_srcs[beg + d];
            cp_async16(slot_base + (uint32_t)d * 512,
                       &P[(size_t)s * WSTR + lid * 4]);
        }
        CP_COMMIT();
    }

    float a0 = 0.f, a1 = 0.f, a2 = 0.f, a3 = 0.f;
    for (int e = beg; e < end; e++) {
        CP_WAIT3();                       // oldest group complete
        int d = (e - beg) & (SPMM_DEPTH - 1);
        float w = g_normv[e];
        float4 val = sbuf[wl][d][lid];
        a0 += w * val.x; a1 += w * val.y; a2 += w * val.z; a3 += w * val.w;
        int en = e + SPMM_DEPTH;
        if (en < end) {
            int s = g_srcs[en];
            cp_async16(slot_base + (uint32_t)d * 512,
                       &P[(size_t)s * WSTR + lid * 4]);
        }
        CP_COMMIT();
    }
    CP_WAIT0();

    float4 o; o.x = a0; o.y = a1; o.z = a2; o.w = a3;
    *(float4*)&PN[(size_t)v * WSTR + lid * 4] = o;
}

// ============================================================================
// Fused layer-3 + output projection.
// ============================================================================
__global__ __launch_bounds__(256) void k_out_fused(
    const float* __restrict__ Wd, float* __restrict__ y)
{
    int tid = threadIdx.x;
    int lid = tid & 31;
    int gwarp  = (blockIdx.x * blockDim.x + tid) >> 5;
    int nwarps = (gridDim.x * blockDim.x) >> 5;

    float2 wf[16];
    #pragma unroll
    for (int blk = 0; blk < 4; blk++)
        #pragma unroll
        for (int j = 0; j < 4; j++) {
            int c = blk * 128 + lid * 4 + j;
            wf[blk * 4 + j] = *(const float2*)&g_wfold[c * 2];
        }
    float yb0 = g_yb[0], yb1 = g_yb[1];

    for (int v = gwarp; v < N_NODES; v += nwarps) {
        const float* row = Wd + (size_t)v * WSTR;
        float s0 = 0.f, s1 = 0.f;
        #pragma unroll
        for (int blk = 0; blk < 4; blk++) {
            float4 hv = *(const float4*)&row[blk * 128 + lid * 4];
            s0 += hv.x * wf[blk * 4 + 0].x + hv.y * wf[blk * 4 + 1].x
                + hv.z * wf[blk * 4 + 2].x + hv.w * wf[blk * 4 + 3].x;
            s1 += hv.x * wf[blk * 4 + 0].y + hv.y * wf[blk * 4 + 1].y
                + hv.z * wf[blk * 4 + 2].y + hv.w * wf[blk * 4 + 3].y;
        }
        #pragma unroll
        for (int o = 16; o > 0; o >>= 1) {
            s0 += __shfl_xor_sync(0xFFFFFFFFu, s0, o);
            s1 += __shfl_xor_sync(0xFFFFFFFFu, s1, o);
        }
        if (lid == 0) {
            y[(size_t)v * 2 + 0] = s0 + yb0;
            y[(size_t)v * 2 + 1] = s1 + yb1;
        }
    }
}

// ============================================================================
// Host launcher — R14 structure (serial main chain, prep fork on s1).
// ============================================================================
extern "C" void kernel_launch(void* const* d_in, const int* in_sizes, int n_in,
                              void* d_out, int out_size)
{
    const float* x    = (const float*)d_in[0];
    const int*   ei   = (const int*)  d_in[1];
    const float* ea   = (const float*)d_in[2];
    const float* eW1  = (const float*)d_in[3];
    const float* eb1  = (const float*)d_in[4];
    const float* eW2  = (const float*)d_in[5];
    const float* eb2  = (const float*)d_in[6];
    const float* tagW = (const float*)d_in[7];
    const float* tagb = (const float*)d_in[8];
    const float* outW = (const float*)d_in[9];
    const float* outb = (const float*)d_in[10];
    float* y = (float*)d_out;

    float *hsum, *wide;
    cudaGetSymbolAddress((void**)&hsum, g_hsum);
    cudaGetSymbolAddress((void**)&wide, g_wide);

    cudaFuncSetAttribute(k_tgemm, cudaFuncAttributeMaxDynamicSharedMemorySize, SM_TOT);

    // stream/event pool — created once (uncaptured correctness call)
    static cudaStream_t s1 = nullptr;
    static cudaEvent_t ev0 = nullptr, ev1 = nullptr;
    if (!s1) {
        cudaStreamCreateWithFlags(&s1, cudaStreamNonBlocking);
        cudaEventCreateWithFlags(&ev0, cudaEventDisableTiming);
        cudaEventCreateWithFlags(&ev1, cudaEventDisableTiming);
    }
    cudaStream_t s0 = 0;

    const int NB_N  = (N_NODES + 255) / 256;
    const int NB_E  = (N_EDGES + 255) / 256;
    const int NB_S  = (N_NODES + 1023) / 1024;   // scan blocks
    const int NB_G  = (N_NODES + 127) / 128;     // gemm CTAs
    const int NB_W  = (N_NODES + 7) / 8;         // warp per node

    // fork: weight prep + per-node MLP precompute concurrent with CSR build
    cudaEventRecord(ev0, s0);
    cudaStreamWaitEvent(s1, ev0, 0);
    k_prepw<<<NCHUNK_TOT, 128, 0, s1>>>(eW2, tagW);
    k_foldw<<<1, 512, 0, s1>>>(tagW, tagb, outW, outb);
    k_xw   <<<NB_W, 256, 0, s1>>>(x, eW1, eb1, wide);

    // CSR build on s0
    k_init <<<NB_N, 256, 0, s0>>>();
    k_count<<<NB_E, 256, 0, s0>>>(ei);
    k_scan1<<<NB_S, 1024, 0, s0>>>();
    k_scan2<<<1, 64, 0, s0>>>(NB_S);
    k_scan3<<<NB_S, 1024, 0, s0>>>();
    k_fill <<<NB_E, 256, 0, s0>>>(ei, ea);

    // join prep into main chain
    cudaEventRecord(ev1, s1);
    cudaStreamWaitEvent(s0, ev1, 0);

    k_edge_mlp<<<NB_W, 256, 0, s0>>>(eW1, wide);

    // h = hsum @ eW2 + deg * eb2   -> wide cols [0,128)
    k_tgemm<<<NB_G, 256, SM_TOT, s0>>>(hsum, H, 2, 0, wide, eb2,
                                       FLAG_BIAS | FLAG_DEGSCALE);

    for (int l = 0; l < L_LAYERS; l++) {
        for (int k = 1; k <= K_HOPS; k++)
            k_spmm<<<NB_W, 256, 0, s0>>>(wide + (k - 1) * H, wide + k * H);
        if (l < L_LAYERS - 1) {
            // h_next = relu([h|p1|p2|p3] @ tagW[l] + b)  -> wide cols [0,128)
            k_tgemm<<<NB_G, 256, SM_TOT, s0>>>(wide, WSTR, 8, 2 + l * 8, wide,
                                               tagb + (size_t)l * H,
                                               FLAG_BIAS | FLAG_RELU);
        }
    }

    // last layer folded through output projection
    k_out_fused<<<NB_W, 256, 0, s0>>>(wide, y);
}

// round 16
// speedup vs baseline: 1.1986x; 1.1986x over previous
#include <cuda_runtime.h>
#include <cuda_bf16.h>
#include <cstdint>

#define N_NODES 50000
#define N_EDGES 600000
#define NFEAT   7
#define EFEAT   4
#define H       128
#define L_LAYERS 4
#define K_HOPS   3
#define WSTR    512               // wide buffer row stride (h|p1|p2|p3)
#define NCHUNK_TOT 34             // 2 (eW2) + 4*8 (tagW layers)

// prepped weight chunk: 32 kpair-rows x 136 u32 (padded) per hi/lo image
#define B_IMG_U32 4352            // 32*136
#define B_CHUNK_U32 (2 * B_IMG_U32)          // 8704 u32 = 34816 B = 2176 x 16B
#define B_CHUNK_V16 2176

// ---------------- scratch (static device globals; no allocation) -------------
__device__ float    g_hsum[N_NODES * H];
__device__ float    g_wide[(size_t)N_NODES * WSTR];
__device__ int      g_deg[N_NODES];
__device__ float    g_dinv[N_NODES];
__device__ int      g_ptr[N_NODES + 1];
__device__ int      g_cur[N_NODES];
__device__ int      g_srcs[N_EDGES];
__device__ float    g_eaperm[(size_t)N_EDGES * 4];   // edge attrs in CSR order
__device__ float    g_normv[N_EDGES];
__device__ int      g_part[64];
__device__ uint32_t g_wprep[(size_t)NCHUNK_TOT * B_CHUNK_U32];
__device__ float    g_wfold[WSTR * 2];       // folded tagW[3]@outW, [512][2]
__device__ float    g_yb[2];                 // folded bias
__device__ float    g_q[(size_t)N_NODES * 8];   // q_k[v][j], k=0..3, j=0..1
__device__ float    g_t0[N_NODES * 2];
__device__ float    g_t1[N_NODES * 2];

#define FLAG_RELU     2
#define FLAG_BIAS     4
#define FLAG_DEGSCALE 8

// ============================================================================
// helpers
// ============================================================================
__device__ __forceinline__ uint32_t smem_u32(const void* p) {
    uint32_t a;
    asm("{ .reg .u64 t; cvta.to.shared.u64 t, %1; cvt.u32.u64 %0, t; }" : "=r"(a) : "l"(p));
    return a;
}
__device__ __forceinline__ void cp_async16(uint32_t saddr, const void* g) {
    asm volatile("cp.async.cg.shared.global [%0], [%1], 16;" :: "r"(saddr), "l"(g) : "memory");
}
#define CP_COMMIT() asm volatile("cp.async.commit_group;" ::: "memory")
#define CP_WAIT0()  asm volatile("cp.async.wait_group 0;" ::: "memory")

// fp32 pair -> (bf16x2 hi word, bf16x2 lo word); element a in low half.
__device__ __forceinline__ void cvt2(float a, float b, uint32_t& hw, uint32_t& lw) {
    __nv_bfloat16 ha = __float2bfloat16_rn(a), hb = __float2bfloat16_rn(b);
    __nv_bfloat162 hp; hp.x = ha; hp.y = hb;
    hw = *(uint32_t*)&hp;
    __nv_bfloat162 lp = __floats2bfloat162_rn(a - __bfloat162float(ha), b - __bfloat162float(hb));
    lw = *(uint32_t*)&lp;
}

__device__ __forceinline__ void mma16816(float* c,
    uint32_t a0, uint32_t a1, uint32_t a2, uint32_t a3, uint32_t b0, uint32_t b1)
{
    asm volatile(
        "mma.sync.aligned.m16n8k16.row.col.f32.bf16.bf16.f32 "
        "{%0,%1,%2,%3},{%4,%5,%6,%7},{%8,%9},{%0,%1,%2,%3};"
        : "+f"(c[0]), "+f"(c[1]), "+f"(c[2]), "+f"(c[3])
        : "r"(a0), "r"(a1), "r"(a2), "r"(a3), "r"(b0), "r"(b1));
}

// ============================================================================
// CSR build
// ============================================================================
__global__ void k_init() {
    int i = blockIdx.x * blockDim.x + threadIdx.x;
    if (i < N_NODES) g_deg[i] = 0;
}
__global__ void k_count(const int* __restrict__ ei) {
    int e = blockIdx.x * blockDim.x + threadIdx.x;
    if (e < N_EDGES) atomicAdd(&g_deg[ei[N_EDGES + e]], 1);
}
// phase 1 of scan; also computes dinv (reads deg anyway)
__global__ void k_scan1() {
    int i = blockIdx.x * 1024 + threadIdx.x;
    int v = (i < N_NODES) ? g_deg[i] : 0;
    if (i < N_NODES) g_dinv[i] = (v > 0) ? rsqrtf((float)v) : 0.0f;
    __shared__ int s[32];
    int l = threadIdx.x & 31, w = threadIdx.x >> 5;
    int t0 = v;
    #pragma unroll
    for (int o = 16; o; o >>= 1) t0 += __shfl_xor_sync(0xFFFFFFFFu, t0, o);
    if (l == 0) s[w] = t0;
    __syncthreads();
    if (threadIdx.x < 32) {
        int t = s[threadIdx.x];
        #pragma unroll
        for (int o = 16; o; o >>= 1) t += __shfl_xor_sync(0xFFFFFFFFu, t, o);
        if (threadIdx.x == 0) g_part[blockIdx.x] = t;
    }
}
// warp-parallel scan of block partials (nblk <= 64)
__global__ void k_scan2(int nblk) {
    int t = threadIdx.x;            // 64 threads
    int l = t & 31, w = t >> 5;
    int v = (t < nblk) ? g_part[t] : 0;
    int x = v;
    #pragma unroll
    for (int o = 1; o < 32; o <<= 1) {
        int u = __shfl_up_sync(0xFFFFFFFFu, x, o);
        if (l >= o) x += u;
    }
    __shared__ int s[2];
    if (l == 31) s[w] = x;
    __syncthreads();
    int incl = x + ((w == 1) ? s[0] : 0);
    if (t < nblk) g_part[t] = incl - v;    // exclusive
    if (t == nblk - 1) g_ptr[N_NODES] = incl;
}
// phase 3: per-node exclusive prefix; also zeroes cursor for k_fill
__global__ void k_scan3() {
    int i = blockIdx.x * 1024 + threadIdx.x;
    int v = (i < N_NODES) ? g_deg[i] : 0;
    int l = threadIdx.x & 31, w = threadIdx.x >> 5;
    int x = v;
    #pragma unroll
    for (int o = 1; o < 32; o <<= 1) { int t = __shfl_up_sync(0xFFFFFFFFu, x, o); if (l >= o) x += t; }
    __shared__ int s[32];
    if (l == 31) s[w] = x;
    __syncthreads();
    if (threadIdx.x < 32) {
        int y = s[threadIdx.x];
        int z = y;
        #pragma unroll
        for (int o = 1; o < 32; o <<= 1) { int t = __shfl_up_sync(0xFFFFFFFFu, z, o); if (threadIdx.x >= o) z += t; }
        s[threadIdx.x] = z - y;
    }
    __syncthreads();
    if (i < N_NODES) {
        g_ptr[i] = g_part[blockIdx.x] + s[w] + x - v;
        g_cur[i] = 0;
    }
}
// fill CSR; also permute edge attrs into CSR order (kills eids indirection)
__global__ void k_fill(const int* __restrict__ ei, const float* __restrict__ ea) {
    int e = blockIdx.x * blockDim.x + threadIdx.x;
    if (e < N_EDGES) {
        int r = ei[e];
        int c = ei[N_EDGES + e];
        int pos = g_ptr[c] + atomicAdd(&g_cur[c], 1);
        g_srcs[pos]  = r;
        g_normv[pos] = g_dinv[r] * g_dinv[c];
        float4 av = *(const float4*)&ea[(size_t)e * 4];
        *(float4*)&g_eaperm[(size_t)pos * 4] = av;
    }
}

// ============================================================================
// Weight prep: per 64-K chunk, build bf16 hi/lo images in b-fragment layout.
// ============================================================================
__global__ __launch_bounds__(128) void k_prepw(const float* __restrict__ eW2,
                                               const float* __restrict__ tagW) {
    int b = blockIdx.x;
    const float* src; int k0;
    if (b < 2) { src = eW2; k0 = b * 64; }
    else { int c = b - 2; src = tagW + (size_t)(c >> 3) * 512 * 128; k0 = (c & 7) * 64; }
    int n = threadIdx.x;
    uint32_t* dh = g_wprep + (size_t)b * B_CHUNK_U32;
    uint32_t* dl = dh + B_IMG_U32;
    #pragma unroll 4
    for (int kp = 0; kp < 32; kp++) {
        float f0 = src[(size_t)(k0 + 2 * kp)     * 128 + n];
        float f1 = src[(size_t)(k0 + 2 * kp + 1) * 128 + n];
        uint32_t hw, lw;
        cvt2(f0, f1, hw, lw);
        dh[kp * 136 + n] = hw;
        dl[kp * 136 + n] = lw;
    }
}

// ============================================================================
// Fold layer-3 weights through the output projection.
// ============================================================================
__global__ __launch_bounds__(512) void k_foldw(
    const float* __restrict__ tagW, const float* __restrict__ tagb,
    const float* __restrict__ outW, const float* __restrict__ outb)
{
    int m = threadIdx.x;   // 0..511
    const float* wrow = tagW + ((size_t)(3 * (K_HOPS + 1)) * H + m) * H;
    float s0 = 0.f, s1 = 0.f;
    #pragma unroll 8
    for (int c = 0; c < H; c++) {
        float t = wrow[c];
        s0 += t * outW[c * 2 + 0];
        s1 += t * outW[c * 2 + 1];
    }
    g_wfold[m * 2 + 0] = s0;
    g_wfold[m * 2 + 1] = s1;
    if (m < 2) {
        float b = outb[m];
        for (int c = 0; c < H; c++) b += tagb[3 * H + c] * outW[c * 2 + m];
        g_yb[m] = b;
    }
}

// ============================================================================
// Per-node precompute for the edge MLP:
//   base[v] = eb1 + x[v] @ W1[0:7]    -> wide cols [256,384)
//   xW[v]   =       x[v] @ W1[7:14]   -> wide cols [128,256)
// ============================================================================
__global__ __launch_bounds__(256) void k_xw(
    const float* __restrict__ x, const float* __restrict__ eW1,
    const float* __restrict__ eb1, float* __restrict__ wide)
{
    __shared__ float sW[14 * H];
    __shared__ float sb[H];
    int tid = threadIdx.x;
    #pragma unroll
    for (int i = 0; i < 7; i++) sW[tid + i * 256] = eW1[tid + i * 256];
    if (tid < H) sb[tid] = eb1[tid];
    __syncthreads();

    int lid = tid & 31;
    int v = (blockIdx.x * blockDim.x + tid) >> 5;
    if (v >= N_NODES) return;

    float xv[7];
    #pragma unroll
    for (int f = 0; f < 7; f++) xv[f] = x[v * NFEAT + f];

    float4 base = *(const float4*)&sb[lid * 4];
    float4 xw = make_float4(0.f, 0.f, 0.f, 0.f);
    #pragma unroll
    for (int f = 0; f < 7; f++) {
        float4 w0 = *(const float4*)&sW[f * H + lid * 4];
        float4 w1 = *(const float4*)&sW[(7 + f) * H + lid * 4];
        base.x += xv[f] * w0.x; base.y += xv[f] * w0.y;
        base.z += xv[f] * w0.z; base.w += xv[f] * w0.w;
        xw.x   += xv[f] * w1.x; xw.y   += xv[f] * w1.y;
        xw.z   += xv[f] * w1.z; xw.w   += xv[f] * w1.w;
    }
    *(float4*)&wide[(size_t)v * WSTR + 256 + lid * 4] = base;
    *(float4*)&wide[(size_t)v * WSTR + 128 + lid * 4] = xw;
}

// ============================================================================
// Edge MLP stage 1 as a gather kernel (proven R12 version).
// ============================================================================
__global__ __launch_bounds__(256) void k_edge_mlp(
    const float* __restrict__ eW1, const float* __restrict__ wide)
{
    int tid = threadIdx.x;
    int lid = tid & 31;
    int v = (blockIdx.x * blockDim.x + tid) >> 5;
    if (v >= N_NODES) return;

    float4 w14 = *(const float4*)&eW1[14 * H + lid * 4];
    float4 w15 = *(const float4*)&eW1[15 * H + lid * 4];
    float4 w16 = *(const float4*)&eW1[16 * H + lid * 4];
    float4 w17 = *(const float4*)&eW1[17 * H + lid * 4];

    float4 base = *(const float4*)&wide[(size_t)v * WSTR + 256 + lid * 4];

    float a0 = 0.f, a1 = 0.f, a2 = 0.f, a3 = 0.f;
    int beg = g_ptr[v], end = g_ptr[v + 1];
    for (int e = beg; e < end; e++) {
        int s = g_srcs[e];
        float4 eav = *(const float4*)&g_eaperm[(size_t)e * 4];
        float4 xwv = *(const float4*)&wide[(size_t)s * WSTR + 128 + lid * 4];
        float d0 = base.x + xwv.x + eav.x * w14.x + eav.y * w15.x + eav.z * w16.x + eav.w * w17.x;
        float d1 = base.y + xwv.y + eav.x * w14.y + eav.y * w15.y + eav.z * w16.y + eav.w * w17.y;
        float d2 = base.z + xwv.z + eav.x * w14.z + eav.y * w15.z + eav.z * w16.z + eav.w * w17.z;
        float d3 = base.w + xwv.w + eav.x * w14.w + eav.y * w15.w + eav.z * w16.w + eav.w * w17.w;
        a0 += fmaxf(d0, 0.f); a1 += fmaxf(d1, 0.f);
        a2 += fmaxf(d2, 0.f); a3 += fmaxf(d3, 0.f);
    }
    float4 o; o.x = a0; o.y = a1; o.z = a2; o.w = a3;
    *(float4*)&g_hsum[(size_t)v * H + lid * 4] = o;
}

// ============================================================================
// Split-bf16 HMMA GEMM, software-pipelined (proven R7/R12 version).
// ============================================================================
#define SM_AH 0
#define SM_AL 18432
#define SM_B0 36864
#define SM_B1 71680
#define SM_TOT 106496

__global__ __launch_bounds__(256) void k_tgemm(
    const float* __restrict__ A, int strideA, int kchunks, int chunkBase,
    float* __restrict__ C, const float* __restrict__ bias, int flags)
{
    extern __shared__ char smem[];
    uint32_t* sAH = (uint32_t*)(smem + SM_AH);
    uint32_t* sAL = (uint32_t*)(smem + SM_AL);

    int tid  = threadIdx.x;
    int lane = tid & 31, wid = tid >> 5;
    int g = lane >> 2, tg = lane & 3;
    int mrow0 = (wid & 1) * 64;
    int ncol0 = (wid >> 1) * 32;

    int row0 = blockIdx.x * 128;

    int sr = tid >> 1;
    int sh = tid & 1;
    bool svalid = (row0 + sr) < N_NODES;
    const float4* arow = (const float4*)(A + (size_t)(row0 + sr) * strideA) + sh * 8;
    uint32_t* ahw = sAH + sr * 36 + sh * 16;
    uint32_t* alw = sAL + sr * 36 + sh * 16;

    uint32_t sbase = smem_u32(smem);

    float acc[4][4][4];
    #pragma unroll
    for (int mt = 0; mt < 4; mt++)
        #pragma unroll
        for (int nt = 0; nt < 4; nt++)
            #pragma unroll
            for (int j = 0; j < 4; j++) acc[mt][nt][j] = 0.f;

    const uint32_t* aHp = sAH + (mrow0 + g) * 36 + tg;
    const uint32_t* aLp = sAL + (mrow0 + g) * 36 + tg;
    const uint32_t* bH[2], *bL[2];
    bH[0] = (const uint32_t*)(smem + SM_B0) + tg * 136 + ncol0 + g;
    bL[0] = bH[0] + B_IMG_U32;
    bH[1] = (const uint32_t*)(smem + SM_B1) + tg * 136 + ncol0 + g;
    bL[1] = bH[1] + B_IMG_U32;

    const char* wsrc = (const char*)(g_wprep + (size_t)chunkBase * B_CHUNK_U32);

    #pragma unroll
    for (int i = 0; i < 9; i++) {
        int idx = tid + i * 256;
        if (idx < B_CHUNK_V16)
            cp_async16(sbase + SM_B0 + idx * 16, wsrc + idx * 16);
    }
    CP_COMMIT();
    float4 aReg[8];
    #pragma unroll
    for (int c = 0; c < 8; c++)
        aReg[c] = svalid ? arow[c] : make_float4(0.f, 0.f, 0.f, 0.f);

    for (int kc = 0; kc < kchunks; kc++) {
        #pragma unroll
        for (int c = 0; c < 8; c++) {
            uint32_t h0, l0, h1, l1;
            cvt2(aReg[c].x, aReg[c].y, h0, l0);
            cvt2(aReg[c].z, aReg[c].w, h1, l1);
            uint2 hv; hv.x = h0; hv.y = h1;
            uint2 lv; lv.x = l0; lv.y = l1;
            *(uint2*)&ahw[c * 2] = hv;
            *(uint2*)&alw[c * 2] = lv;
        }
        CP_WAIT0();
        __syncthreads();

        if (kc + 1 < kchunks) {
            uint32_t sdst = sbase + (((kc + 1) & 1) ? SM_B1 : SM_B0);
            const char* wn = wsrc + (size_t)(kc + 1) * (B_CHUNK_U32 * 4);
            #pragma unroll
            for (int i = 0; i < 9; i++) {
                int idx = tid + i * 256;
                if (idx < B_CHUNK_V16)
                    cp_async16(sdst + idx * 16, wn + idx * 16);
            }
            CP_COMMIT();
            const float4* ap = arow + (kc + 1) * 16;
            #pragma unroll
            for (int c = 0; c < 8; c++)
                aReg[c] = svalid ? ap[c] : make_float4(0.f, 0.f, 0.f, 0.f);
        }

        const uint32_t* bHp = bH[kc & 1];
        const uint32_t* bLp = bL[kc & 1];
        #pragma unroll
        for (int ks = 0; ks < 4; ks++) {
            uint32_t ah[4][4], al[4][4];
            #pragma unroll
            for (int mt = 0; mt < 4; mt++) {
                int b0 = mt * 16 * 36 + ks * 8;
                ah[mt][0] = aHp[b0];            ah[mt][1] = aHp[b0 + 8 * 36];
                ah[mt][2] = aHp[b0 + 4];        ah[mt][3] = aHp[b0 + 8 * 36 + 4];
                al[mt][0] = aLp[b0];            al[mt][1] = aLp[b0 + 8 * 36];
                al[mt][2] = aLp[b0 + 4];        al[mt][3] = aLp[b0 + 8 * 36 + 4];
            }
            #pragma unroll
            for (int nt = 0; nt < 4; nt++) {
                int bb = ks * 8 * 136 + nt * 8;
                uint32_t bh0 = bHp[bb], bh1 = bHp[bb + 4 * 136];
                uint32_t bl0 = bLp[bb], bl1 = bLp[bb + 4 * 136];
                #pragma unroll
                for (int mt = 0; mt < 4; mt++) {
                    mma16816(acc[mt][nt], ah[mt][0], ah[mt][1], ah[mt][2], ah[mt][3], bh0, bh1);
                    mma16816(acc[mt][nt], ah[mt][0], ah[mt][1], ah[mt][2], ah[mt][3], bl0, bl1);
                    mma16816(acc[mt][nt], al[mt][0], al[mt][1], al[mt][2], al[mt][3], bh0, bh1);
                }
            }
        }
        __syncthreads();
    }

    #pragma unroll
    for (int mt = 0; mt < 4; mt++) {
        #pragma unroll
        for (int half = 0; half < 2; half++) {
            int r = row0 + mrow0 + mt * 16 + g + half * 8;
            if (r >= N_NODES) continue;
            float degs = 1.0f;
            if (flags & FLAG_DEGSCALE) degs = (float)g_deg[r];
            float* crow = C + (size_t)r * WSTR;
            #pragma unroll
            for (int nt = 0; nt < 4; nt++) {
                int col = ncol0 + nt * 8 + tg * 2;
                float v0 = acc[mt][nt][half * 2 + 0];
                float v1 = acc[mt][nt][half * 2 + 1];
                if (flags & FLAG_BIAS) {
                    v0 += bias[col]     * degs;
                    v1 += bias[col + 1] * degs;
                }
                if (flags & FLAG_RELU) { v0 = fmaxf(v0, 0.f); v1 = fmaxf(v1, 0.f); }
                float2 o; o.x = v0; o.y = v1;
                *(float2*)&crow[col] = o;
            }
        }
    }
}

// ============================================================================
// SpMM hop on the wide buffer (plain serial loop — proven fastest; three
// "clever" variants all regressed).
// ============================================================================
__global__ __launch_bounds__(256) void k_spmm(
    const float* __restrict__ P, float* __restrict__ PN)
{
    int tid = threadIdx.x;
    int lid = tid & 31;
    int gwarp  = (blockIdx.x * blockDim.x + tid) >> 5;
    int nwarps = (gridDim.x * blockDim.x) >> 5;

    for (int v = gwarp; v < N_NODES; v += nwarps) {
        float a0 = 0.f, a1 = 0.f, a2 = 0.f, a3 = 0.f;
        int beg = g_ptr[v], end = g_ptr[v + 1];
        for (int e = beg; e < end; e++) {
            int s = g_srcs[e];
            float w = g_normv[e];
            float4 val = *(const float4*)&P[(size_t)s * WSTR + lid * 4];
            a0 += w * val.x; a1 += w * val.y; a2 += w * val.z; a3 += w * val.w;
        }
        float4 o; o.x = a0; o.y = a1; o.z = a2; o.w = a3;
        *(float4*)&PN[(size_t)v * WSTR + lid * 4] = o;
    }
}

// ============================================================================
// q-fold: q_k[v][j] = sum_c h[v][c] * Wfold[k*128+c][j]   (k=0..3, j=0..1)
// Warp per node; one pass over h. Replaces k_out_fused's projection.
// ============================================================================
__global__ __launch_bounds__(256) void k_qfold(const float* __restrict__ Wd)
{
    int tid = threadIdx.x;
    int lid = tid & 31;
    int v = (blockIdx.x * blockDim.x + tid) >> 5;
    if (v >= N_NODES) return;

    float4 hv = *(const float4*)&Wd[(size_t)v * WSTR + lid * 4];
    float hvv[4] = {hv.x, hv.y, hv.z, hv.w};

    float acc[8];
    #pragma unroll
    for (int i = 0; i < 8; i++) acc[i] = 0.f;

    #pragma unroll
    for (int k = 0; k < 4; k++) {
        #pragma unroll
        for (int jj = 0; jj < 4; jj++) {
            int c = k * 128 + lid * 4 + jj;
            float2 wf = *(const float2*)&g_wfold[c * 2];
            acc[k * 2 + 0] += hvv[jj] * wf.x;
            acc[k * 2 + 1] += hvv[jj] * wf.y;
        }
    }
    #pragma unroll
    for (int o = 16; o > 0; o >>= 1) {
        #pragma unroll
        for (int i = 0; i < 8; i++)
            acc[i] += __shfl_xor_sync(0xFFFFFFFFu, acc[i], o);
    }
    if (lid < 8) g_q[(size_t)v * 8 + lid] = acc[lid];
}

// ============================================================================
// Narrow (2-col) SpMM: out[v] = add[v] + sum_e norm[e] * in[src]  (+yb)
// Thread per node; tiny gathers, fully latency-hidden by thread count.
// ============================================================================
__global__ __launch_bounds__(256) void k_spmm2(
    const float* __restrict__ in2, int strideIn,
    const float* __restrict__ add2, int strideAdd,
    float* __restrict__ out2, int strideOut, int addYb)
{
    int v = blockIdx.x * blockDim.x + threadIdx.x;
    if (v >= N_NODES) return;

    float a0 = add2[(size_t)v * strideAdd + 0];
    float a1 = add2[(size_t)v * strideAdd + 1];
    int beg = g_ptr[v], end = g_ptr[v + 1];
    for (int e = beg; e < end; e++) {
        int s = g_srcs[e];
        float w = g_normv[e];
        a0 += w * in2[(size_t)s * strideIn + 0];
        a1 += w * in2[(size_t)s * strideIn + 1];
    }
    if (addYb) { a0 += g_yb[0]; a1 += g_yb[1]; }
    out2[(size_t)v * strideOut + 0] = a0;
    out2[(size_t)v * strideOut + 1] = a1;
}

// ============================================================================
// Host launcher — R14 structure; last layer via narrow Horner cascade:
//   y = q0 + A(q1 + A(q2 + A q3)) + yb
// ============================================================================
extern "C" void kernel_launch(void* const* d_in, const int* in_sizes, int n_in,
                              void* d_out, int out_size)
{
    const float* x    = (const float*)d_in[0];
    const int*   ei   = (const int*)  d_in[1];
    const float* ea   = (const float*)d_in[2];
    const float* eW1  = (const float*)d_in[3];
    const float* eb1  = (const float*)d_in[4];
    const float* eW2  = (const float*)d_in[5];
    const float* eb2  = (const float*)d_in[6];
    const float* tagW = (const float*)d_in[7];
    const float* tagb = (const float*)d_in[8];
    const float* outW = (const float*)d_in[9];
    const float* outb = (const float*)d_in[10];
    float* y = (float*)d_out;

    float *hsum, *wide, *q, *t0, *t1;
    cudaGetSymbolAddress((void**)&hsum, g_hsum);
    cudaGetSymbolAddress((void**)&wide, g_wide);
    cudaGetSymbolAddress((void**)&q,    g_q);
    cudaGetSymbolAddress((void**)&t0,   g_t0);
    cudaGetSymbolAddress((void**)&t1,   g_t1);

    cudaFuncSetAttribute(k_tgemm, cudaFuncAttributeMaxDynamicSharedMemorySize, SM_TOT);

    // stream/event pool — created once (uncaptured correctness call)
    static cudaStream_t s1 = nullptr;
    static cudaEvent_t ev0 = nullptr, ev1 = nullptr;
    if (!s1) {
        cudaStreamCreateWithFlags(&s1, cudaStreamNonBlocking);
        cudaEventCreateWithFlags(&ev0, cudaEventDisableTiming);
        cudaEventCreateWithFlags(&ev1, cudaEventDisableTiming);
    }
    cudaStream_t s0 = 0;

    const int NB_N  = (N_NODES + 255) / 256;
    const int NB_E  = (N_EDGES + 255) / 256;
    const int NB_S  = (N_NODES + 1023) / 1024;   // scan blocks
    const int NB_G  = (N_NODES + 127) / 128;     // gemm CTAs
    const int NB_W  = (N_NODES + 7) / 8;         // warp per node

    // fork: weight prep + per-node MLP precompute concurrent with CSR build
    cudaEventRecord(ev0, s0);
    cudaStreamWaitEvent(s1, ev0, 0);
    k_prepw<<<NCHUNK_TOT, 128, 0, s1>>>(eW2, tagW);
    k_foldw<<<1, 512, 0, s1>>>(tagW, tagb, outW, outb);
    k_xw   <<<NB_W, 256, 0, s1>>>(x, eW1, eb1, wide);

    // CSR build on s0
    k_init <<<NB_N, 256, 0, s0>>>();
    k_count<<<NB_E, 256, 0, s0>>>(ei);
    k_scan1<<<NB_S, 1024, 0, s0>>>();
    k_scan2<<<1, 64, 0, s0>>>(NB_S);
    k_scan3<<<NB_S, 1024, 0, s0>>>();
    k_fill <<<NB_E, 256, 0, s0>>>(ei, ea);

    // join prep into main chain
    cudaEventRecord(ev1, s1);
    cudaStreamWaitEvent(s0, ev1, 0);

    k_edge_mlp<<<NB_W, 256, 0, s0>>>(eW1, wide);

    // h = hsum @ eW2 + deg * eb2   -> wide cols [0,128)
    k_tgemm<<<NB_G, 256, SM_TOT, s0>>>(hsum, H, 2, 0, wide, eb2,
                                       FLAG_BIAS | FLAG_DEGSCALE);

    // layers 0-2: wide hops + fused K=512 GEMM
    for (int l = 0; l < 3; l++) {
        for (int k = 1; k <= K_HOPS; k++)
            k_spmm<<<NB_W, 256, 0, s0>>>(wide + (k - 1) * H, wide + k * H);
        k_tgemm<<<NB_G, 256, SM_TOT, s0>>>(wide, WSTR, 8, 2 + l * 8, wide,
                                           tagb + (size_t)l * H,
                                           FLAG_BIAS | FLAG_RELU);
    }

    // layer 3: project first (q_k = h @ Wfold_k), then 2-col Horner hops
    k_qfold<<<NB_W, 256, 0, s0>>>(wide);
    k_spmm2<<<NB_N, 256, 0, s0>>>(q + 6, 8, q + 4, 8, t0, 2, 0);  // t0 = q2 + A q3
    k_spmm2<<<NB_N, 256, 0, s0>>>(t0, 2, q + 2, 8, t1, 2, 0);     // t1 = q1 + A t0
    k_spmm2<<<NB_N, 256, 0, s0>>>(t1, 2, q + 0, 8, y, 2, 1);      // y  = q0 + A t1 + yb
}

// round 17
// speedup vs baseline: 1.2110x; 1.0104x over previous
#include <cuda_runtime.h>
#include <cuda_bf16.h>
#include <cstdint>

#define N_NODES 50000
#define N_EDGES 600000
#define NFEAT   7
#define EFEAT   4
#define H       128
#define L_LAYERS 4
#define K_HOPS   3
#define WSTR    512               // wide buffer row stride (h|p1|p2|p3)
#define NCHUNK_TOT 34             // 2 (eW2) + 4*8 (tagW layers)

// prepped weight chunk: 32 kpair-rows x 136 u32 (padded) per hi/lo image
#define B_IMG_U32 4352            // 32*136
#define B_CHUNK_U32 (2 * B_IMG_U32)          // 8704 u32 = 34816 B = 2176 x 16B
#define B_CHUNK_V16 2176

#define GATHER_CTAS 1184          // 8 CTAs/SM x 148 SMs (2048-thread residency)

// ---------------- scratch (static device globals; no allocation) -------------
__device__ float    g_hsum[N_NODES * H];
__device__ float    g_wide[(size_t)N_NODES * WSTR];
__device__ int      g_deg[N_NODES];
__device__ float    g_dinv[N_NODES];
__device__ int      g_ptr[N_NODES + 1];
__device__ int      g_cur[N_NODES];
__device__ int      g_srcs[N_EDGES];
__device__ float    g_eaperm[(size_t)N_EDGES * 4];   // edge attrs in CSR order
__device__ float    g_normv[N_EDGES];
__device__ int      g_part[64];
__device__ uint32_t g_wprep[(size_t)NCHUNK_TOT * B_CHUNK_U32];
__device__ float    g_wfold[WSTR * 2];       // folded tagW[3]@outW, [512][2]
__device__ float    g_yb[2];                 // folded bias
__device__ float    g_q[(size_t)N_NODES * 8];   // q_k[v][j], k=0..3, j=0..1
__device__ float    g_t0[N_NODES * 2];
__device__ float    g_t1[N_NODES * 2];

#define FLAG_RELU     2
#define FLAG_BIAS     4
#define FLAG_DEGSCALE 8

// ============================================================================
// helpers
// ============================================================================
__device__ __forceinline__ uint32_t smem_u32(const void* p) {
    uint32_t a;
    asm("{ .reg .u64 t; cvta.to.shared.u64 t, %1; cvt.u32.u64 %0, t; }" : "=r"(a) : "l"(p));
    return a;
}
__device__ __forceinline__ void cp_async16(uint32_t saddr, const void* g) {
    asm volatile("cp.async.cg.shared.global [%0], [%1], 16;" :: "r"(saddr), "l"(g) : "memory");
}
#define CP_COMMIT() asm volatile("cp.async.commit_group;" ::: "memory")
#define CP_WAIT0()  asm volatile("cp.async.wait_group 0;" ::: "memory")

// fp32 pair -> (bf16x2 hi word, bf16x2 lo word); element a in low half.
__device__ __forceinline__ void cvt2(float a, float b, uint32_t& hw, uint32_t& lw) {
    __nv_bfloat16 ha = __float2bfloat16_rn(a), hb = __float2bfloat16_rn(b);
    __nv_bfloat162 hp; hp.x = ha; hp.y = hb;
    hw = *(uint32_t*)&hp;
    __nv_bfloat162 lp = __floats2bfloat162_rn(a - __bfloat162float(ha), b - __bfloat162float(hb));
    lw = *(uint32_t*)&lp;
}

__device__ __forceinline__ void mma16816(float* c,
    uint32_t a0, uint32_t a1, uint32_t a2, uint32_t a3, uint32_t b0, uint32_t b1)
{
    asm volatile(
        "mma.sync.aligned.m16n8k16.row.col.f32.bf16.bf16.f32 "
        "{%0,%1,%2,%3},{%4,%5,%6,%7},{%8,%9},{%0,%1,%2,%3};"
        : "+f"(c[0]), "+f"(c[1]), "+f"(c[2]), "+f"(c[3])
        : "r"(a0), "r"(a1), "r"(a2), "r"(a3), "r"(b0), "r"(b1));
}

// ============================================================================
// CSR build
// ============================================================================
__global__ void k_init() {
    int i = blockIdx.x * blockDim.x + threadIdx.x;
    if (i < N_NODES) g_deg[i] = 0;
}
__global__ void k_count(const int* __restrict__ ei) {
    int e = blockIdx.x * blockDim.x + threadIdx.x;
    if (e < N_EDGES) atomicAdd(&g_deg[ei[N_EDGES + e]], 1);
}
// phase 1 of scan; also computes dinv (reads deg anyway)
__global__ void k_scan1() {
    int i = blockIdx.x * 1024 + threadIdx.x;
    int v = (i < N_NODES) ? g_deg[i] : 0;
    if (i < N_NODES) g_dinv[i] = (v > 0) ? rsqrtf((float)v) : 0.0f;
    __shared__ int s[32];
    int l = threadIdx.x & 31, w = threadIdx.x >> 5;
    int t0 = v;
    #pragma unroll
    for (int o = 16; o; o >>= 1) t0 += __shfl_xor_sync(0xFFFFFFFFu, t0, o);
    if (l == 0) s[w] = t0;
    __syncthreads();
    if (threadIdx.x < 32) {
        int t = s[threadIdx.x];
        #pragma unroll
        for (int o = 16; o; o >>= 1) t += __shfl_xor_sync(0xFFFFFFFFu, t, o);
        if (threadIdx.x == 0) g_part[blockIdx.x] = t;
    }
}
// phase 3 (merged with old scan2): every block scans the <=64 partials in
// smem (two warps), then does its per-node exclusive prefix; zeroes cursor.
__global__ void k_scan3(int nblk) {
    int tid = threadIdx.x;
    int l = tid & 31, w = tid >> 5;

    // two-warp scan of block partials (threads 0..63)
    __shared__ int wsum[2];
    __shared__ int spart[64];
    int pv = 0, px = 0;
    if (tid < 64) {
        pv = (tid < nblk) ? g_part[tid] : 0;
        px = pv;
        #pragma unroll
        for (int o = 1; o < 32; o <<= 1) {
            int u = __shfl_up_sync(0xFFFFFFFFu, px, o);
            if (l >= o) px += u;
        }
        if (l == 31) wsum[w] = px;
    }
    __syncthreads();
    if (tid < 64) {
        int incl = px + ((w == 1) ? wsum[0] : 0);
        spart[tid] = incl - pv;          // exclusive
        if (blockIdx.x == 0 && tid == nblk - 1) g_ptr[N_NODES] = incl;
    }
    __syncthreads();

    // per-node exclusive prefix within this block
    int i = blockIdx.x * 1024 + tid;
    int v = (i < N_NODES) ? g_deg[i] : 0;
    int x = v;
    #pragma unroll
    for (int o = 1; o < 32; o <<= 1) { int t = __shfl_up_sync(0xFFFFFFFFu, x, o); if (l >= o) x += t; }
    __shared__ int s[32];
    if (l == 31) s[w] = x;
    __syncthreads();
    if (tid < 32) {
        int y = s[tid];
        int z = y;
        #pragma unroll
        for (int o = 1; o < 32; o <<= 1) { int t = __shfl_up_sync(0xFFFFFFFFu, z, o); if (tid >= o) z += t; }
        s[tid] = z - y;
    }
    __syncthreads();
    if (i < N_NODES) {
        g_ptr[i] = spart[blockIdx.x] + s[w] + x - v;
        g_cur[i] = 0;
    }
}
// fill CSR; also permute edge attrs into CSR order (kills eids indirection)
__global__ void k_fill(const int* __restrict__ ei, const float* __restrict__ ea) {
    int e = blockIdx.x * blockDim.x + threadIdx.x;
    if (e < N_EDGES) {
        int r = ei[e];
        int c = ei[N_EDGES + e];
        int pos = g_ptr[c] + atomicAdd(&g_cur[c], 1);
        g_srcs[pos]  = r;
        g_normv[pos] = g_dinv[r] * g_dinv[c];
        float4 av = *(const float4*)&ea[(size_t)e * 4];
        *(float4*)&g_eaperm[(size_t)pos * 4] = av;
    }
}

// ============================================================================
// Weight prep: per 64-K chunk, build bf16 hi/lo images in b-fragment layout.
// ============================================================================
__global__ __launch_bounds__(128) void k_prepw(const float* __restrict__ eW2,
                                               const float* __restrict__ tagW) {
    int b = blockIdx.x;
    const float* src; int k0;
    if (b < 2) { src = eW2; k0 = b * 64; }
    else { int c = b - 2; src = tagW + (size_t)(c >> 3) * 512 * 128; k0 = (c & 7) * 64; }
    int n = threadIdx.x;
    uint32_t* dh = g_wprep + (size_t)b * B_CHUNK_U32;
    uint32_t* dl = dh + B_IMG_U32;
    #pragma unroll 4
    for (int kp = 0; kp < 32; kp++) {
        float f0 = src[(size_t)(k0 + 2 * kp)     * 128 + n];
        float f1 = src[(size_t)(k0 + 2 * kp + 1) * 128 + n];
        uint32_t hw, lw;
        cvt2(f0, f1, hw, lw);
        dh[kp * 136 + n] = hw;
        dl[kp * 136 + n] = lw;
    }
}

// ============================================================================
// Fold layer-3 weights through the output projection.
// ============================================================================
__global__ __launch_bounds__(512) void k_foldw(
    const float* __restrict__ tagW, const float* __restrict__ tagb,
    const float* __restrict__ outW, const float* __restrict__ outb)
{
    int m = threadIdx.x;   // 0..511
    const float* wrow = tagW + ((size_t)(3 * (K_HOPS + 1)) * H + m) * H;
    float s0 = 0.f, s1 = 0.f;
    #pragma unroll 8
    for (int c = 0; c < H; c++) {
        float t = wrow[c];
        s0 += t * outW[c * 2 + 0];
        s1 += t * outW[c * 2 + 1];
    }
    g_wfold[m * 2 + 0] = s0;
    g_wfold[m * 2 + 1] = s1;
    if (m < 2) {
        float b = outb[m];
        for (int c = 0; c < H; c++) b += tagb[3 * H + c] * outW[c * 2 + m];
        g_yb[m] = b;
    }
}

// ============================================================================
// Per-node precompute for the edge MLP:
//   base[v] = eb1 + x[v] @ W1[0:7]    -> wide cols [256,384)
//   xW[v]   =       x[v] @ W1[7:14]   -> wide cols [128,256)
// ============================================================================
__global__ __launch_bounds__(256) void k_xw(
    const float* __restrict__ x, const float* __restrict__ eW1,
    const float* __restrict__ eb1, float* __restrict__ wide)
{
    __shared__ float sW[14 * H];
    __shared__ float sb[H];
    int tid = threadIdx.x;
    #pragma unroll
    for (int i = 0; i < 7; i++) sW[tid + i * 256] = eW1[tid + i * 256];
    if (tid < H) sb[tid] = eb1[tid];
    __syncthreads();

    int lid = tid & 31;
    int v = (blockIdx.x * blockDim.x + tid) >> 5;
    if (v >= N_NODES) return;

    float xv[7];
    #pragma unroll
    for (int f = 0; f < 7; f++) xv[f] = x[v * NFEAT + f];

    float4 base = *(const float4*)&sb[lid * 4];
    float4 xw = make_float4(0.f, 0.f, 0.f, 0.f);
    #pragma unroll
    for (int f = 0; f < 7; f++) {
        float4 w0 = *(const float4*)&sW[f * H + lid * 4];
        float4 w1 = *(const float4*)&sW[(7 + f) * H + lid * 4];
        base.x += xv[f] * w0.x; base.y += xv[f] * w0.y;
        base.z += xv[f] * w0.z; base.w += xv[f] * w0.w;
        xw.x   += xv[f] * w1.x; xw.y   += xv[f] * w1.y;
        xw.z   += xv[f] * w1.z; xw.w   += xv[f] * w1.w;
    }
    *(float4*)&wide[(size_t)v * WSTR + 256 + lid * 4] = base;
    *(float4*)&wide[(size_t)v * WSTR + 128 + lid * 4] = xw;
}

// ============================================================================
// Edge MLP stage 1 as a gather kernel — grid-stride (GATHER_CTAS), warp/node.
// ============================================================================
__global__ __launch_bounds__(256) void k_edge_mlp(
    const float* __restrict__ eW1, const float* __restrict__ wide)
{
    int tid = threadIdx.x;
    int lid = tid & 31;
    int gwarp  = (blockIdx.x * blockDim.x + tid) >> 5;
    int nwarps = (gridDim.x * blockDim.x) >> 5;

    float4 w14 = *(const float4*)&eW1[14 * H + lid * 4];
    float4 w15 = *(const float4*)&eW1[15 * H + lid * 4];
    float4 w16 = *(const float4*)&eW1[16 * H + lid * 4];
    float4 w17 = *(const float4*)&eW1[17 * H + lid * 4];

    for (int v = gwarp; v < N_NODES; v += nwarps) {
        float4 base = *(const float4*)&wide[(size_t)v * WSTR + 256 + lid * 4];
        float a0 = 0.f, a1 = 0.f, a2 = 0.f, a3 = 0.f;
        int beg = g_ptr[v], end = g_ptr[v + 1];
        for (int e = beg; e < end; e++) {
            int s = g_srcs[e];
            float4 eav = *(const float4*)&g_eaperm[(size_t)e * 4];
            float4 xwv = *(const float4*)&wide[(size_t)s * WSTR + 128 + lid * 4];
            float d0 = base.x + xwv.x + eav.x * w14.x + eav.y * w15.x + eav.z * w16.x + eav.w * w17.x;
            float d1 = base.y + xwv.y + eav.x * w14.y + eav.y * w15.y + eav.z * w16.y + eav.w * w17.y;
            float d2 = base.z + xwv.z + eav.x * w14.z + eav.y * w15.z + eav.z * w16.z + eav.w * w17.z;
            float d3 = base.w + xwv.w + eav.x * w14.w + eav.y * w15.w + eav.z * w16.w + eav.w * w17.w;
            a0 += fmaxf(d0, 0.f); a1 += fmaxf(d1, 0.f);
            a2 += fmaxf(d2, 0.f); a3 += fmaxf(d3, 0.f);
        }
        float4 o; o.x = a0; o.y = a1; o.z = a2; o.w = a3;
        *(float4*)&g_hsum[(size_t)v * H + lid * 4] = o;
    }
}

// ============================================================================
// Split-bf16 HMMA GEMM, software-pipelined (proven R7/R12 version).
// ============================================================================
#define SM_AH 0
#define SM_AL 18432
#define SM_B0 36864
#define SM_B1 71680
#define SM_TOT 106496

__global__ __launch_bounds__(256) void k_tgemm(
    const float* __restrict__ A, int strideA, int kchunks, int chunkBase,
    float* __restrict__ C, const float* __restrict__ bias, int flags)
{
    extern __shared__ char smem[];
    uint32_t* sAH = (uint32_t*)(smem + SM_AH);
    uint32_t* sAL = (uint32_t*)(smem + SM_AL);

    int tid  = threadIdx.x;
    int lane = tid & 31, wid = tid >> 5;
    int g = lane >> 2, tg = lane & 3;
    int mrow0 = (wid & 1) * 64;
    int ncol0 = (wid >> 1) * 32;

    int row0 = blockIdx.x * 128;

    int sr = tid >> 1;
    int sh = tid & 1;
    bool svalid = (row0 + sr) < N_NODES;
    const float4* arow = (const float4*)(A + (size_t)(row0 + sr) * strideA) + sh * 8;
    uint32_t* ahw = sAH + sr * 36 + sh * 16;
    uint32_t* alw = sAL + sr * 36 + sh * 16;

    uint32_t sbase = smem_u32(smem);

    float acc[4][4][4];
    #pragma unroll
    for (int mt = 0; mt < 4; mt++)
        #pragma unroll
        for (int nt = 0; nt < 4; nt++)
            #pragma unroll
            for (int j = 0; j < 4; j++) acc[mt][nt][j] = 0.f;

    const uint32_t* aHp = sAH + (mrow0 + g) * 36 + tg;
    const uint32_t* aLp = sAL + (mrow0 + g) * 36 + tg;
    const uint32_t* bH[2], *bL[2];
    bH[0] = (const uint32_t*)(smem + SM_B0) + tg * 136 + ncol0 + g;
    bL[0] = bH[0] + B_IMG_U32;
    bH[1] = (const uint32_t*)(smem + SM_B1) + tg * 136 + ncol0 + g;
    bL[1] = bH[1] + B_IMG_U32;

    const char* wsrc = (const char*)(g_wprep + (size_t)chunkBase * B_CHUNK_U32);

    #pragma unroll
    for (int i = 0; i < 9; i++) {
        int idx = tid + i * 256;
        if (idx < B_CHUNK_V16)
            cp_async16(sbase + SM_B0 + idx * 16, wsrc + idx * 16);
    }
    CP_COMMIT();
    float4 aReg[8];
    #pragma unroll
    for (int c = 0; c < 8; c++)
        aReg[c] = svalid ? arow[c] : make_float4(0.f, 0.f, 0.f, 0.f);

    for (int kc = 0; kc < kchunks; kc++) {
        #pragma unroll
        for (int c = 0; c < 8; c++) {
            uint32_t h0, l0, h1, l1;
            cvt2(aReg[c].x, aReg[c].y, h0, l0);
            cvt2(aReg[c].z, aReg[c].w, h1, l1);
            uint2 hv; hv.x = h0; hv.y = h1;
            uint2 lv; lv.x = l0; lv.y = l1;
            *(uint2*)&ahw[c * 2] = hv;
            *(uint2*)&alw[c * 2] = lv;
        }
        CP_WAIT0();
        __syncthreads();

        if (kc + 1 < kchunks) {
            uint32_t sdst = sbase + (((kc + 1) & 1) ? SM_B1 : SM_B0);
            const char* wn = wsrc + (size_t)(kc + 1) * (B_CHUNK_U32 * 4);
            #pragma unroll
            for (int i = 0; i < 9; i++) {
                int idx = tid + i * 256;
                if (idx < B_CHUNK_V16)
                    cp_async16(sdst + idx * 16, wn + idx * 16);
            }
            CP_COMMIT();
            const float4* ap = arow + (kc + 1) * 16;
            #pragma unroll
            for (int c = 0; c < 8; c++)
                aReg[c] = svalid ? ap[c] : make_float4(0.f, 0.f, 0.f, 0.f);
        }

        const uint32_t* bHp = bH[kc & 1];
        const uint32_t* bLp = bL[kc & 1];
        #pragma unroll
        for (int ks = 0; ks < 4; ks++) {
            uint32_t ah[4][4], al[4][4];
            #pragma unroll
            for (int mt = 0; mt < 4; mt++) {
                int b0 = mt * 16 * 36 + ks * 8;
                ah[mt][0] = aHp[b0];            ah[mt][1] = aHp[b0 + 8 * 36];
                ah[mt][2] = aHp[b0 + 4];        ah[mt][3] = aHp[b0 + 8 * 36 + 4];
                al[mt][0] = aLp[b0];            al[mt][1] = aLp[b0 + 8 * 36];
                al[mt][2] = aLp[b0 + 4];        al[mt][3] = aLp[b0 + 8 * 36 + 4];
            }
            #pragma unroll
            for (int nt = 0; nt < 4; nt++) {
                int bb = ks * 8 * 136 + nt * 8;
                uint32_t bh0 = bHp[bb], bh1 = bHp[bb + 4 * 136];
                uint32_t bl0 = bLp[bb], bl1 = bLp[bb + 4 * 136];
                #pragma unroll
                for (int mt = 0; mt < 4; mt++) {
                    mma16816(acc[mt][nt], ah[mt][0], ah[mt][1], ah[mt][2], ah[mt][3], bh0, bh1);
                    mma16816(acc[mt][nt], ah[mt][0], ah[mt][1], ah[mt][2], ah[mt][3], bl0, bl1);
                    mma16816(acc[mt][nt], al[mt][0], al[mt][1], al[mt][2], al[mt][3], bh0, bh1);
                }
            }
        }
        __syncthreads();
    }

    #pragma unroll
    for (int mt = 0; mt < 4; mt++) {
        #pragma unroll
        for (int half = 0; half < 2; half++) {
            int r = row0 + mrow0 + mt * 16 + g + half * 8;
            if (r >= N_NODES) continue;
            float degs = 1.0f;
            if (flags & FLAG_DEGSCALE) degs = (float)g_deg[r];
            float* crow = C + (size_t)r * WSTR;
            #pragma unroll
            for (int nt = 0; nt < 4; nt++) {
                int col = ncol0 + nt * 8 + tg * 2;
                float v0 = acc[mt][nt][half * 2 + 0];
                float v1 = acc[mt][nt][half * 2 + 1];
                if (flags & FLAG_BIAS) {
                    v0 += bias[col]     * degs;
                    v1 += bias[col + 1] * degs;
                }
                if (flags & FLAG_RELU) { v0 = fmaxf(v0, 0.f); v1 = fmaxf(v1, 0.f); }
                float2 o; o.x = v0; o.y = v1;
                *(float2*)&crow[col] = o;
            }
        }
    }
}

// ============================================================================
// SpMM hop on the wide buffer (plain serial loop — proven fastest; now
// launched with GATHER_CTAS so each warp streams ~5-6 nodes, amortizing ramp).
// ============================================================================
__global__ __launch_bounds__(256) void k_spmm(
    const float* __restrict__ P, float* __restrict__ PN)
{
    int tid = threadIdx.x;
    int lid = tid & 31;
    int gwarp  = (blockIdx.x * blockDim.x + tid) >> 5;
    int nwarps = (gridDim.x * blockDim.x) >> 5;

    for (int v = gwarp; v < N_NODES; v += nwarps) {
        float a0 = 0.f, a1 = 0.f, a2 = 0.f, a3 = 0.f;
        int beg = g_ptr[v], end = g_ptr[v + 1];
        for (int e = beg; e < end; e++) {
            int s = g_srcs[e];
            float w = g_normv[e];
            float4 val = *(const float4*)&P[(size_t)s * WSTR + lid * 4];
            a0 += w * val.x; a1 += w * val.y; a2 += w * val.z; a3 += w * val.w;
        }
        float4 o; o.x = a0; o.y = a1; o.z = a2; o.w = a3;
        *(float4*)&PN[(size_t)v * WSTR + lid * 4] = o;
    }
}

// ============================================================================
// q-fold: q_k[v][j] = sum_c h[v][c] * Wfold[k*128+c][j]   (k=0..3, j=0..1)
// ============================================================================
__global__ __launch_bounds__(256) void k_qfold(const float* __restrict__ Wd)
{
    int tid = threadIdx.x;
    int lid = tid & 31;
    int v = (blockIdx.x * blockDim.x + tid) >> 5;
    if (v >= N_NODES) return;

    float4 hv = *(const float4*)&Wd[(size_t)v * WSTR + lid * 4];
    float hvv[4] = {hv.x, hv.y, hv.z, hv.w};

    float acc[8];
    #pragma unroll
    for (int i = 0; i < 8; i++) acc[i] = 0.f;

    #pragma unroll
    for (int k = 0; k < 4; k++) {
        #pragma unroll
        for (int jj = 0; jj < 4; jj++) {
            int c = k * 128 + lid * 4 + jj;
            float2 wf = *(const float2*)&g_wfold[c * 2];
            acc[k * 2 + 0] += hvv[jj] * wf.x;
            acc[k * 2 + 1] += hvv[jj] * wf.y;
        }
    }
    #pragma unroll
    for (int o = 16; o > 0; o >>= 1) {
        #pragma unroll
        for (int i = 0; i < 8; i++)
            acc[i] += __shfl_xor_sync(0xFFFFFFFFu, acc[i], o);
    }
    if (lid < 8) g_q[(size_t)v * 8 + lid] = acc[lid];
}

// ============================================================================
// Narrow (2-col) SpMM: out[v] = add[v] + sum_e norm[e] * in[src]  (+yb)
// ============================================================================
__global__ __launch_bounds__(256) void k_spmm2(
    const float* __restrict__ in2, int strideIn,
    const float* __restrict__ add2, int strideAdd,
    float* __restrict__ out2, int strideOut, int addYb)
{
    int v = blockIdx.x * blockDim.x + threadIdx.x;
    if (v >= N_NODES) return;

    float a0 = add2[(size_t)v * strideAdd + 0];
    float a1 = add2[(size_t)v * strideAdd + 1];
    int beg = g_ptr[v], end = g_ptr[v + 1];
    for (int e = beg; e < end; e++) {
        int s = g_srcs[e];
        float w = g_normv[e];
        a0 += w * in2[(size_t)s * strideIn + 0];
        a1 += w * in2[(size_t)s * strideIn + 1];
    }
    if (addYb) { a0 += g_yb[0]; a1 += g_yb[1]; }
    out2[(size_t)v * strideOut + 0] = a0;
    out2[(size_t)v * strideOut + 1] = a1;
}

// ============================================================================
// Host launcher — R16 structure; scan2 merged into scan3, gather kernels
// launched persistent-ish (GATHER_CTAS).
// ============================================================================
extern "C" void kernel_launch(void* const* d_in, const int* in_sizes, int n_in,
                              void* d_out, int out_size)
{
    const float* x    = (const float*)d_in[0];
    const int*   ei   = (const int*)  d_in[1];
    const float* ea   = (const float*)d_in[2];
    const float* eW1  = (const float*)d_in[3];
    const float* eb1  = (const float*)d_in[4];
    const float* eW2  = (const float*)d_in[5];
    const float* eb2  = (const float*)d_in[6];
    const float* tagW = (const float*)d_in[7];
    const float* tagb = (const float*)d_in[8];
    const float* outW = (const float*)d_in[9];
    const float* outb = (const float*)d_in[10];
    float* y = (float*)d_out;

    float *hsum, *wide, *q, *t0, *t1;
    cudaGetSymbolAddress((void**)&hsum, g_hsum);
    cudaGetSymbolAddress((void**)&wide, g_wide);
    cudaGetSymbolAddress((void**)&q,    g_q);
    cudaGetSymbolAddress((void**)&t0,   g_t0);
    cudaGetSymbolAddress((void**)&t1,   g_t1);

    cudaFuncSetAttribute(k_tgemm, cudaFuncAttributeMaxDynamicSharedMemorySize, SM_TOT);

    // stream/event pool — created once (uncaptured correctness call)
    static cudaStream_t s1 = nullptr;
    static cudaEvent_t ev0 = nullptr, ev1 = nullptr;
    if (!s1) {
        cudaStreamCreateWithFlags(&s1, cudaStreamNonBlocking);
        cudaEventCreateWithFlags(&ev0, cudaEventDisableTiming);
        cudaEventCreateWithFlags(&ev1, cudaEventDisableTiming);
    }
    cudaStream_t s0 = 0;

    const int NB_N  = (N_NODES + 255) / 256;
    const int NB_E  = (N_EDGES + 255) / 256;
    const int NB_S  = (N_NODES + 1023) / 1024;   // scan blocks
    const int NB_G  = (N_NODES + 127) / 128;     // gemm CTAs
    const int NB_W  = (N_NODES + 7) / 8;         // warp per node

    // fork: weight prep + per-node MLP precompute concurrent with CSR build
    cudaEventRecord(ev0, s0);
    cudaStreamWaitEvent(s1, ev0, 0);
    k_prepw<<<NCHUNK_TOT, 128, 0, s1>>>(eW2, tagW);
    k_foldw<<<1, 512, 0, s1>>>(tagW, tagb, outW, outb);
    k_xw   <<<NB_W, 256, 0, s1>>>(x, eW1, eb1, wide);

    // CSR build on s0
    k_init <<<NB_N, 256, 0, s0>>>();
    k_count<<<NB_E, 256, 0, s0>>>(ei);
    k_scan1<<<NB_S, 1024, 0, s0>>>();
    k_scan3<<<NB_S, 1024, 0, s0>>>(NB_S);
    k_fill <<<NB_E, 256, 0, s0>>>(ei, ea);

    // join prep into main chain
    cudaEventRecord(ev1, s1);
    cudaStreamWaitEvent(s0, ev1, 0);

    k_edge_mlp<<<GATHER_CTAS, 256, 0, s0>>>(eW1, wide);

    // h = hsum @ eW2 + deg * eb2   -> wide cols [0,128)
    k_tgemm<<<NB_G, 256, SM_TOT, s0>>>(hsum, H, 2, 0, wide, eb2,
                                       FLAG_BIAS | FLAG_DEGSCALE);

    // layers 0-2: wide hops + fused K=512 GEMM
    for (int l = 0; l < 3; l++) {
        for (int k = 1; k <= K_HOPS; k++)
            k_spmm<<<GATHER_CTAS, 256, 0, s0>>>(wide + (k - 1) * H, wide + k * H);
        k_tgemm<<<NB_G, 256, SM_TOT, s0>>>(wide, WSTR, 8, 2 + l * 8, wide,
                                           tagb + (size_t)l * H,
                                           FLAG_BIAS | FLAG_RELU);
    }

    // layer 3: project first (q_k = h @ Wfold_k), then 2-col Horner hops
    k_qfold<<<NB_W, 256, 0, s0>>>(wide);
    k_spmm2<<<NB_N, 256, 0, s0>>>(q + 6, 8, q + 4, 8, t0, 2, 0);  // t0 = q2 + A q3
    k_spmm2<<<NB_N, 256, 0, s0>>>(t0, 2, q + 2, 8, t1, 2, 0);     // t1 = q1 + A t0
    k_spmm2<<<NB_N, 256, 0, s0>>>(t1, 2, q + 0, 8, y, 2, 1);      // y  = q0 + A t1 + yb
}